// round 11
// baseline (speedup 1.0000x reference)
#include <cuda_runtime.h>
#include <math.h>
#include <stdint.h>

// ChamferLoss via exact pruned NN, v7: 4 queries per lane (128 per warp) to
// amortize each shared-memory candidate fetch over 4 queries (crossbar-bound).
// batch=64, k=2048 2-D points (x = cols [0,2048), y = cols [2048,4096)).
// Fixed bucket range [-8,8), 256 bins. Exact: per-query min over a proven
// covering superset (bucket-edge vote bound; clamped edge buckets keep
// one-sided containment) == brute force bitwise, scatter-order invariant.
// Deterministic: results by original index, fixed-order sums, fused finalize.

#define K        2048
#define BATCH    64
#define THREADS  512
#define NWARPS   16
#define PPT      4                  // points per thread per side (sort phase)
#define NBINS    256
#define NBLOCKS  (2 * BATCH)
#define XMIN     (-8.0f)
#define INVW     16.0f              // NBINS / 16
#define WB       0.0625f            // bucket width

#define SMEM_D_BYTES   (K * 16)     // float4: 32 KB
#define SMEM_Q_BYTES   (K * 8)      // float2: 16 KB
#define SMEM_QI_BYTES  (K * 2)      // short:   4 KB
#define DYN_SMEM       (SMEM_D_BYTES + SMEM_Q_BYTES + SMEM_QI_BYTES)

__device__ float g_partials[NBLOCKS];
__device__ unsigned int g_count = 0;

__global__ __launch_bounds__(THREADS, 1)
void chamfer_nn_kernel(const float* __restrict__ pred,
                       const float* __restrict__ targ,
                       float* __restrict__ out)
{
    extern __shared__ unsigned char dynsmem[];
    float4* shD  = (float4*)dynsmem;                              // sorted DB (x,y,x2+y2,0)
    float2* shQ  = (float2*)(dynsmem + SMEM_D_BYTES);             // sorted queries
    short*  shQi = (short*)(dynsmem + SMEM_D_BYTES + SMEM_Q_BYTES);

    __shared__ int   cntD[NBINS], cntQ[NBINS];     // histogram -> scatter cursors
    __shared__ int   offD[NBINS + 1];
    __shared__ float red[NWARPS];
    __shared__ int   lastflag;

    const int bx    = blockIdx.x;
    const int batch = bx >> 1;
    const int dir   = bx & 1;
    const int tid   = threadIdx.x;
    const int wg    = tid >> 5, lane = tid & 31;

    const float* q_base = (dir == 0 ? pred : targ) + batch * (2 * K);
    const float* d_base = (dir == 0 ? targ : pred) + batch * (2 * K);

    // ---- Load both sides (coalesced); fixed bucket range ----
    float Dx[PPT], Dy[PPT], Qx[PPT], Qy[PPT];
    #pragma unroll
    for (int r = 0; r < PPT; ++r) {
        int j = r * THREADS + tid;
        Dx[r] = d_base[j];  Dy[r] = d_base[j + K];
        Qx[r] = q_base[j];  Qy[r] = q_base[j + K];
    }

    if (tid < NBINS) { cntD[tid] = 0; cntQ[tid] = 0; }
    __syncthreads();

    int bD[PPT], bQ[PPT];
    #pragma unroll
    for (int r = 0; r < PPT; ++r) {
        bD[r] = min(NBINS - 1, max(0, (int)((Dx[r] - XMIN) * INVW)));
        atomicAdd(&cntD[bD[r]], 1);
        bQ[r] = min(NBINS - 1, max(0, (int)((Qx[r] - XMIN) * INVW)));
        atomicAdd(&cntQ[bQ[r]], 1);
    }
    __syncthreads();

    // ---- Exclusive prefix over 256 bins (warp 0: D + offD; warp 1: Q) ----
    if (wg < 2) {
        int* cnt = (wg == 0) ? cntD : cntQ;
        int c[8], s = 0;
        #pragma unroll
        for (int i = 0; i < 8; ++i) { c[i] = cnt[lane * 8 + i]; s += c[i]; }
        int e = s;
        #pragma unroll
        for (int o = 1; o < 32; o <<= 1) {
            int n = __shfl_up_sync(0xFFFFFFFF, e, o);
            if (lane >= o) e += n;
        }
        int run = e - s;
        #pragma unroll
        for (int i = 0; i < 8; ++i) {
            if (wg == 0) offD[lane * 8 + i] = run;
            cnt[lane * 8 + i] = run;
            run += c[i];
        }
        if (wg == 0 && lane == 31) offD[NBINS] = e;   // = K
    }
    __syncthreads();

    // ---- Scatter into bucket order ----
    #pragma unroll
    for (int r = 0; r < PPT; ++r) {
        int p = atomicAdd(&cntD[bD[r]], 1);
        shD[p] = make_float4(Dx[r], Dy[r], fmaf(Dx[r], Dx[r], Dy[r] * Dy[r]), 0.0f);
        p = atomicAdd(&cntQ[bQ[r]], 1);
        shQ[p]  = make_float2(Qx[r], Qy[r]);
        shQi[p] = (short)(r * THREADS + tid);
    }
    __syncthreads();

    // ---- Scan: warp wg owns 128 consecutive sorted queries, 4 per lane ----
    const int qbase = wg * 128 + 4 * lane;
    const float4 qp0 = *(const float4*)&shQ[qbase];       // queries 0,1 (x,y,x,y)
    const float4 qp1 = *(const float4*)&shQ[qbase + 2];   // queries 2,3
    const short4 qi  = *(const short4*)&shQi[qbase];

    const float ax0 = -2.0f * qp0.x, ay0 = -2.0f * qp0.y;
    const float ax1 = -2.0f * qp0.z, ay1 = -2.0f * qp0.w;
    const float ax2 = -2.0f * qp1.x, ay2 = -2.0f * qp1.y;
    const float ax3 = -2.0f * qp1.z, ay3 = -2.0f * qp1.w;
    const float q20 = fmaf(qp0.x, qp0.x, qp0.y * qp0.y);
    const float q21 = fmaf(qp0.z, qp0.z, qp0.w * qp0.w);
    const float q22 = fmaf(qp1.x, qp1.x, qp1.y * qp1.y);
    const float q23 = fmaf(qp1.z, qp1.z, qp1.w * qp1.w);
    const float qxmn = fminf(fminf(qp0.x, qp0.z), fminf(qp1.x, qp1.z));
    const float qxmx = fmaxf(fmaxf(qp0.x, qp0.z), fmaxf(qp1.x, qp1.z));

    int bmn = min(NBINS - 1, max(0, (int)((qxmn - XMIN) * INVW)));
    int bmx = min(NBINS - 1, max(0, (int)((qxmx - XMIN) * INVW)));
    const int bl = __reduce_min_sync(0xFFFFFFFF, bmn);
    const int bh = __reduce_max_sync(0xFFFFFFFF, bmx);

    float mnA0 = INFINITY, mnB0 = INFINITY;
    float mnA1 = INFINITY, mnB1 = INFINITY;
    float mnA2 = INFINITY, mnB2 = INFINITY;
    float mnA3 = INFINITY, mnB3 = INFINITY;

    // Phase 1: contiguous neighborhood, unroll 2 (2 LDS.128 in flight,
    // each candidate serves 4 queries).
    {
        const int lo = offD[max(bl - 1, 0)];
        const int hi = offD[min(bh + 1, NBINS - 1) + 1];
        int idx = lo;
        for (; idx + 2 <= hi; idx += 2) {
            float4 t0 = shD[idx], t1 = shD[idx + 1];
            mnA0 = fminf(mnA0, fmaf(ax0, t0.x, fmaf(ay0, t0.y, t0.z)));
            mnA1 = fminf(mnA1, fmaf(ax1, t0.x, fmaf(ay1, t0.y, t0.z)));
            mnA2 = fminf(mnA2, fmaf(ax2, t0.x, fmaf(ay2, t0.y, t0.z)));
            mnA3 = fminf(mnA3, fmaf(ax3, t0.x, fmaf(ay3, t0.y, t0.z)));
            mnB0 = fminf(mnB0, fmaf(ax0, t1.x, fmaf(ay0, t1.y, t1.z)));
            mnB1 = fminf(mnB1, fmaf(ax1, t1.x, fmaf(ay1, t1.y, t1.z)));
            mnB2 = fminf(mnB2, fmaf(ax2, t1.x, fmaf(ay2, t1.y, t1.z)));
            mnB3 = fminf(mnB3, fmaf(ax3, t1.x, fmaf(ay3, t1.y, t1.z)));
        }
        if (idx < hi) {
            float4 t = shD[idx];
            mnA0 = fminf(mnA0, fmaf(ax0, t.x, fmaf(ay0, t.y, t.z)));
            mnA1 = fminf(mnA1, fmaf(ax1, t.x, fmaf(ay1, t.y, t.z)));
            mnA2 = fminf(mnA2, fmaf(ax2, t.x, fmaf(ay2, t.y, t.z)));
            mnA3 = fminf(mnA3, fmaf(ax3, t.x, fmaf(ay3, t.y, t.z)));
        }
    }

    // Left expansion: per-bucket warp vote.
    for (int l = bl - 2; l >= 0; --l) {
        float best = fmaxf(fmaxf(q20 + fminf(mnA0, mnB0), q21 + fminf(mnA1, mnB1)),
                           fmaxf(q22 + fminf(mnA2, mnB2), q23 + fminf(mnA3, mnB3)));
        float gap  = qxmn - (XMIN + (float)(l + 1) * WB);
        bool need  = (gap <= 0.0f) || (gap * gap < best);
        if (!__any_sync(0xFFFFFFFF, need)) break;
        const int lo = offD[l], hi = offD[l + 1];
        for (int idx = lo; idx < hi; ++idx) {
            float4 t = shD[idx];
            mnA0 = fminf(mnA0, fmaf(ax0, t.x, fmaf(ay0, t.y, t.z)));
            mnA1 = fminf(mnA1, fmaf(ax1, t.x, fmaf(ay1, t.y, t.z)));
            mnA2 = fminf(mnA2, fmaf(ax2, t.x, fmaf(ay2, t.y, t.z)));
            mnA3 = fminf(mnA3, fmaf(ax3, t.x, fmaf(ay3, t.y, t.z)));
        }
    }
    // Right expansion.
    for (int r = bh + 2; r < NBINS; ++r) {
        float best = fmaxf(fmaxf(q20 + fminf(mnA0, mnB0), q21 + fminf(mnA1, mnB1)),
                           fmaxf(q22 + fminf(mnA2, mnB2), q23 + fminf(mnA3, mnB3)));
        float gap  = (XMIN + (float)r * WB) - qxmx;
        bool need  = (gap <= 0.0f) || (gap * gap < best);
        if (!__any_sync(0xFFFFFFFF, need)) break;
        const int lo = offD[r], hi = offD[r + 1];
        for (int idx = lo; idx < hi; ++idx) {
            float4 t = shD[idx];
            mnB0 = fminf(mnB0, fmaf(ax0, t.x, fmaf(ay0, t.y, t.z)));
            mnB1 = fminf(mnB1, fmaf(ax1, t.x, fmaf(ay1, t.y, t.z)));
            mnB2 = fminf(mnB2, fmaf(ax2, t.x, fmaf(ay2, t.y, t.z)));
            mnB3 = fminf(mnB3, fmaf(ax3, t.x, fmaf(ay3, t.y, t.z)));
        }
    }

    const float res0 = sqrtf(fmaxf(q20 + fminf(mnA0, mnB0), 0.0f));
    const float res1 = sqrtf(fmaxf(q21 + fminf(mnA1, mnB1), 0.0f));
    const float res2 = sqrtf(fmaxf(q22 + fminf(mnA2, mnB2), 0.0f));
    const float res3 = sqrtf(fmaxf(q23 + fminf(mnA3, mnB3), 0.0f));
    __syncthreads();     // all warps done reading shD/shQ before overwrite

    // ---- Scatter results to original order (reuse shD), fixed-order sum ----
    float* rslt = (float*)shD;
    rslt[qi.x] = res0;
    rslt[qi.y] = res1;
    rslt[qi.z] = res2;
    rslt[qi.w] = res3;
    __syncthreads();

    float s = 0.0f;
    #pragma unroll
    for (int r = 0; r < PPT; ++r)
        s += rslt[tid + r * THREADS];
    #pragma unroll
    for (int o = 16; o > 0; o >>= 1)
        s += __shfl_xor_sync(0xFFFFFFFF, s, o);
    if (lane == 0) red[wg] = s;
    __syncthreads();

    float v = 0.0f;
    if (tid < 32) {
        v = (tid < NWARPS) ? red[tid] : 0.0f;
        #pragma unroll
        for (int o = 8; o > 0; o >>= 1)
            v += __shfl_down_sync(0xFFFFFFFF, v, o);
    }

    // ---- Fused finalize: last block sums the 128 partials ----
    if (tid == 0) {
        g_partials[bx] = v;
        __threadfence();
        unsigned old = atomicAdd(&g_count, 1u);
        lastflag = (old == NBLOCKS - 1);
    }
    __syncthreads();
    if (lastflag && tid < 32) {
        volatile float* gp = g_partials;
        float t = 0.0f;
        #pragma unroll
        for (int i = 0; i < NBLOCKS / 32; ++i)
            t += gp[i * 32 + tid];
        #pragma unroll
        for (int o = 16; o > 0; o >>= 1)
            t += __shfl_down_sync(0xFFFFFFFF, t, o);
        if (tid == 0) {
            out[0] = t * (1.0f / ((float)K * (float)BATCH));
            g_count = 0;   // reset for next graph replay
        }
    }
}

extern "C" void kernel_launch(void* const* d_in, const int* in_sizes, int n_in,
                              void* d_out, int out_size)
{
    const float* pred = (const float*)d_in[0];
    const float* targ = (const float*)d_in[1];
    float* out = (float*)d_out;

    cudaFuncSetAttribute(chamfer_nn_kernel,
                         cudaFuncAttributeMaxDynamicSharedMemorySize, DYN_SMEM);
    chamfer_nn_kernel<<<NBLOCKS, THREADS, DYN_SMEM>>>(pred, targ, out);
}

// round 12
// speedup vs baseline: 1.0078x; 1.0078x over previous
#include <cuda_runtime.h>
#include <math.h>
#include <stdint.h>

// ChamferLoss via exact pruned NN, v8: R7 scan shape (32 warps x 64-query
// groups, 2 queries/lane) + fixed range (no min/max prologue) + 512 fine
// buckets + lazy phase-1 ([bl,bh] only; vote-expansion supplies the rest).
// batch=64, k=2048 2-D points (x = cols [0,2048), y = cols [2048,4096)).
// Exact: per-query min over a proven covering superset (bucket-edge vote
// bound; clamped edge buckets keep one-sided containment) == brute force
// bitwise, scatter-order invariant. Deterministic: results by original
// index, fixed-order sums, fused last-block finalize.

#define K        2048
#define BATCH    64
#define THREADS  1024
#define NWARPS   32
#define PPT      2                  // points per thread per side (sort phase)
#define NBINS    512
#define BPL      (NBINS / 32)       // bins per lane in prefix (16)
#define NBLOCKS  (2 * BATCH)
#define XMIN     (-8.0f)
#define INVW     32.0f              // NBINS / 16
#define WB       0.03125f           // bucket width

#define SMEM_D_BYTES   (K * 16)     // float4: 32 KB
#define SMEM_Q_BYTES   (K * 8)      // float2: 16 KB
#define SMEM_QI_BYTES  (K * 2)      // short:   4 KB
#define DYN_SMEM       (SMEM_D_BYTES + SMEM_Q_BYTES + SMEM_QI_BYTES)

__device__ float g_partials[NBLOCKS];
__device__ unsigned int g_count = 0;

__global__ __launch_bounds__(THREADS, 1)
void chamfer_nn_kernel(const float* __restrict__ pred,
                       const float* __restrict__ targ,
                       float* __restrict__ out)
{
    extern __shared__ unsigned char dynsmem[];
    float4* shD  = (float4*)dynsmem;                              // sorted DB (x,y,x2+y2,0)
    float2* shQ  = (float2*)(dynsmem + SMEM_D_BYTES);             // sorted queries
    short*  shQi = (short*)(dynsmem + SMEM_D_BYTES + SMEM_Q_BYTES);

    __shared__ int   cntD[NBINS], cntQ[NBINS];     // histogram -> scatter cursors
    __shared__ int   offD[NBINS + 1];
    __shared__ float red[NWARPS];
    __shared__ int   lastflag;

    const int bx    = blockIdx.x;
    const int batch = bx >> 1;
    const int dir   = bx & 1;
    const int tid   = threadIdx.x;
    const int wg    = tid >> 5, lane = tid & 31;

    const float* q_base = (dir == 0 ? pred : targ) + batch * (2 * K);
    const float* d_base = (dir == 0 ? targ : pred) + batch * (2 * K);

    // ---- Load both sides (coalesced); fixed bucket range, no reductions ----
    float Dx[PPT], Dy[PPT], Qx[PPT], Qy[PPT];
    #pragma unroll
    for (int r = 0; r < PPT; ++r) {
        int j = r * THREADS + tid;
        Dx[r] = d_base[j];  Dy[r] = d_base[j + K];
        Qx[r] = q_base[j];  Qy[r] = q_base[j + K];
    }

    if (tid < NBINS) { cntD[tid] = 0; cntQ[tid] = 0; }
    __syncthreads();

    int bD[PPT], bQ[PPT];
    #pragma unroll
    for (int r = 0; r < PPT; ++r) {
        bD[r] = min(NBINS - 1, max(0, (int)((Dx[r] - XMIN) * INVW)));
        atomicAdd(&cntD[bD[r]], 1);
        bQ[r] = min(NBINS - 1, max(0, (int)((Qx[r] - XMIN) * INVW)));
        atomicAdd(&cntQ[bQ[r]], 1);
    }
    __syncthreads();

    // ---- Exclusive prefix over 512 bins (warp 0: D + offD; warp 1: Q) ----
    if (wg < 2) {
        int* cnt = (wg == 0) ? cntD : cntQ;
        int c[BPL], s = 0;
        #pragma unroll
        for (int i = 0; i < BPL; ++i) { c[i] = cnt[lane * BPL + i]; s += c[i]; }
        int e = s;
        #pragma unroll
        for (int o = 1; o < 32; o <<= 1) {
            int n = __shfl_up_sync(0xFFFFFFFF, e, o);
            if (lane >= o) e += n;
        }
        int run = e - s;
        #pragma unroll
        for (int i = 0; i < BPL; ++i) {
            if (wg == 0) offD[lane * BPL + i] = run;
            cnt[lane * BPL + i] = run;
            run += c[i];
        }
        if (wg == 0 && lane == 31) offD[NBINS] = e;   // = K
    }
    __syncthreads();

    // ---- Scatter into bucket order ----
    #pragma unroll
    for (int r = 0; r < PPT; ++r) {
        int p = atomicAdd(&cntD[bD[r]], 1);
        shD[p] = make_float4(Dx[r], Dy[r], fmaf(Dx[r], Dx[r], Dy[r] * Dy[r]), 0.0f);
        p = atomicAdd(&cntQ[bQ[r]], 1);
        shQ[p]  = make_float2(Qx[r], Qy[r]);
        shQi[p] = (short)(r * THREADS + tid);
    }
    __syncthreads();

    // ---- Scan: warp wg owns 64 consecutive sorted queries, 2 per lane ----
    const int pairidx = wg * 32 + lane;
    const float4 qq = *(const float4*)&shQ[2 * pairidx];
    const short2 qi = ((const short2*)shQi)[pairidx];

    const float ax0 = -2.0f * qq.x, ay0 = -2.0f * qq.y;
    const float ax1 = -2.0f * qq.z, ay1 = -2.0f * qq.w;
    const float q20 = fmaf(qq.x, qq.x, qq.y * qq.y);
    const float q21 = fmaf(qq.z, qq.z, qq.w * qq.w);
    const float qxmn = fminf(qq.x, qq.z);
    const float qxmx = fmaxf(qq.x, qq.z);

    int b0 = min(NBINS - 1, max(0, (int)((qq.x - XMIN) * INVW)));
    int b1 = min(NBINS - 1, max(0, (int)((qq.z - XMIN) * INVW)));
    const int bl = __reduce_min_sync(0xFFFFFFFF, min(b0, b1));
    const int bh = __reduce_max_sync(0xFFFFFFFF, max(b0, b1));

    float mnA0 = INFINITY, mnB0 = INFINITY;
    float mnA1 = INFINITY, mnB1 = INFINITY;

    // Phase 1: the group's own buckets only (lazy seed; expansion does the rest)
    {
        const int lo = offD[bl], hi = offD[bh + 1];
        int idx = lo;
        for (; idx + 2 <= hi; idx += 2) {
            float4 t0 = shD[idx], t1 = shD[idx + 1];
            mnA0 = fminf(mnA0, fmaf(ax0, t0.x, fmaf(ay0, t0.y, t0.z)));
            mnA1 = fminf(mnA1, fmaf(ax1, t0.x, fmaf(ay1, t0.y, t0.z)));
            mnB0 = fminf(mnB0, fmaf(ax0, t1.x, fmaf(ay0, t1.y, t1.z)));
            mnB1 = fminf(mnB1, fmaf(ax1, t1.x, fmaf(ay1, t1.y, t1.z)));
        }
        if (idx < hi) {
            float4 t = shD[idx];
            mnA0 = fminf(mnA0, fmaf(ax0, t.x, fmaf(ay0, t.y, t.z)));
            mnA1 = fminf(mnA1, fmaf(ax1, t.x, fmaf(ay1, t.y, t.z)));
        }
    }

    // Left expansion: per-bucket warp vote, stop when no lane can improve.
    for (int l = bl - 1; l >= 0; --l) {
        float best = fmaxf(q20 + fminf(mnA0, mnB0), q21 + fminf(mnA1, mnB1));
        float gap  = qxmn - (XMIN + (float)(l + 1) * WB);
        bool need  = (gap <= 0.0f) || (gap * gap < best);
        if (!__any_sync(0xFFFFFFFF, need)) break;
        const int lo = offD[l], hi = offD[l + 1];
        for (int idx = lo; idx < hi; ++idx) {
            float4 t = shD[idx];
            mnA0 = fminf(mnA0, fmaf(ax0, t.x, fmaf(ay0, t.y, t.z)));
            mnA1 = fminf(mnA1, fmaf(ax1, t.x, fmaf(ay1, t.y, t.z)));
        }
    }
    // Right expansion.
    for (int r = bh + 1; r < NBINS; ++r) {
        float best = fmaxf(q20 + fminf(mnA0, mnB0), q21 + fminf(mnA1, mnB1));
        float gap  = (XMIN + (float)r * WB) - qxmx;
        bool need  = (gap <= 0.0f) || (gap * gap < best);
        if (!__any_sync(0xFFFFFFFF, need)) break;
        const int lo = offD[r], hi = offD[r + 1];
        for (int idx = lo; idx < hi; ++idx) {
            float4 t = shD[idx];
            mnB0 = fminf(mnB0, fmaf(ax0, t.x, fmaf(ay0, t.y, t.z)));
            mnB1 = fminf(mnB1, fmaf(ax1, t.x, fmaf(ay1, t.y, t.z)));
        }
    }

    const float res0 = sqrtf(fmaxf(q20 + fminf(mnA0, mnB0), 0.0f));
    const float res1 = sqrtf(fmaxf(q21 + fminf(mnA1, mnB1), 0.0f));
    __syncthreads();     // all warps done reading shD/shQ before overwrite

    // ---- Scatter results to original order (reuse shD), fixed-order sum ----
    float* rslt = (float*)shD;
    rslt[qi.x] = res0;
    rslt[qi.y] = res1;
    __syncthreads();

    float s = rslt[tid] + rslt[tid + THREADS];
    #pragma unroll
    for (int o = 16; o > 0; o >>= 1)
        s += __shfl_xor_sync(0xFFFFFFFF, s, o);
    if (lane == 0) red[wg] = s;
    __syncthreads();

    float v = 0.0f;
    if (tid < 32) {
        v = red[tid];
        #pragma unroll
        for (int o = 16; o > 0; o >>= 1)
            v += __shfl_down_sync(0xFFFFFFFF, v, o);
    }

    // ---- Fused finalize: last block sums the 128 partials ----
    if (tid == 0) {
        g_partials[bx] = v;
        __threadfence();
        unsigned old = atomicAdd(&g_count, 1u);
        lastflag = (old == NBLOCKS - 1);
    }
    __syncthreads();
    if (lastflag && tid < 32) {
        volatile float* gp = g_partials;
        float t = 0.0f;
        #pragma unroll
        for (int i = 0; i < NBLOCKS / 32; ++i)
            t += gp[i * 32 + tid];
        #pragma unroll
        for (int o = 16; o > 0; o >>= 1)
            t += __shfl_down_sync(0xFFFFFFFF, t, o);
        if (tid == 0) {
            out[0] = t * (1.0f / ((float)K * (float)BATCH));
            g_count = 0;   // reset for next graph replay
        }
    }
}

extern "C" void kernel_launch(void* const* d_in, const int* in_sizes, int n_in,
                              void* d_out, int out_size)
{
    const float* pred = (const float*)d_in[0];
    const float* targ = (const float*)d_in[1];
    float* out = (float*)d_out;

    cudaFuncSetAttribute(chamfer_nn_kernel,
                         cudaFuncAttributeMaxDynamicSharedMemorySize, DYN_SMEM);
    chamfer_nn_kernel<<<NBLOCKS, THREADS, DYN_SMEM>>>(pred, targ, out);
}